// round 5
// baseline (speedup 1.0000x reference)
#include <cuda_runtime.h>
#include <math.h>

#define BB 4
#define NN 20480
#define KK 16
#define NPTS (BB*NN)   // 81920

// ---------------- scratch (device globals, no allocation) ----------------
__device__ float g_featT[NPTS*16];
__device__ float g_feat0[NPTS*16];
__device__ float g_feat1[NPTS*16];
__device__ float g_lrep[(size_t)NPTS*KK*16];
__device__ float g_gdis[NPTS*KK];
__device__ float g_lg[NPTS];
__device__ float g_h[(size_t)NPTS*128];

// preprocessed weights
__device__ float g_wm1[256];
__device__ float g_wlm1p[192];
__device__ float g_wlm2[256];
__device__ float g_p1fc[1152];
__device__ float g_wp1mt[512];
__device__ float g_p2fc[1152];
__device__ float g_wp2mt[1024];
__device__ float g_m2t[2048];
__device__ float g_sct[1024];
__device__ float g_m3t[256];
__device__ float g_m4t[8192];

// ---------------- prep ----------------------------------------------------
__global__ void k_prep(const float* m1W,const float* m1g,
                       const float* lm1W,const float* lm1g,
                       const float* lm2W,const float* lm2g,
                       const float* p1fcW,
                       const float* p1mW,const float* p1mg,
                       const float* p2fcW,
                       const float* p2mW,const float* p2mg,
                       const float* m2W,const float* m2g,
                       const float* scW,const float* scg,
                       const float* m3W,const float* m3g,
                       const float* m4W,const float* m4g)
{
  int t=threadIdx.x;
  for(int i=t;i<256;i+=256)  g_wm1[i]=m1g[i>>4]*m1W[i];
  for(int i=t;i<192;i+=256){
    int o=i/12,c=i%12;
    g_wlm1p[i]=(c<9)? lm1g[o]*lm1W[o*9+c] : 0.f;
  }
  for(int i=t;i<256;i+=256)  g_wlm2[i]=lm2g[i>>4]*lm2W[i];
  for(int i=t;i<1152;i+=256){
    int o=i/36,c=i%36; float v=0.f;
    if(c==0) v=p1fcW[o*34];
    else if(c==1) v=2.f*p1fcW[o*34+1];
    else if(c>=4) v=p1fcW[o*34+2+(c-4)];
    g_p1fc[i]=v;
  }
  for(int i=t;i<512;i+=256){ int c=i>>4,o=i&15; g_wp1mt[i]=p1mg[o]*p1mW[o*32+c]; }
  for(int i=t;i<1152;i+=256){
    int o=i/36,c=i%36; float v=0.f;
    if(c==0) v=p2fcW[o*34];
    else if(c==1) v=2.f*p2fcW[o*34+1];
    else if(c>=4) v=p2fcW[o*34+2+(c-4)];
    g_p2fc[i]=v;
  }
  for(int i=t;i<512;i+=256){
    int c=i>>4,j=i&15;
    g_wp2mt[2*i]  =p2mg[j]   *p2mW[j*32+c];
    g_wp2mt[2*i+1]=p2mg[j+16]*p2mW[(j+16)*32+c];
  }
  for(int i=t;i<2048;i+=256){int o=i>>5,c=i&31;  g_m2t[c*64+o]=m2g[o]*m2W[i];}
  for(int i=t;i<1024;i+=256){int o=i>>4,c=i&15;  g_sct[c*64+o]=scg[o]*scW[i];}
  for(int i=t;i<256;i+=256) {int o=i>>2,c=i&3;   g_m3t[c*64+o]=m3g[o]*m3W[i];}
  for(int i=t;i<8192;i+=256){int o=i>>7,c=i&127; g_m4t[c*64+o]=m4g[o]*m4W[i];}
}

// ---------------- kernel A ------------------------------------------------
__global__ void __launch_bounds__(256) kA(const float* __restrict__ feature,
                                          const float* __restrict__ m1b){
  __shared__ __align__(16) float sW[256];
  __shared__ float sb[16];
  int t=threadIdx.x;
  if(t<256) sW[t]=g_wm1[t];
  if(t<16)  sb[t]=m1b[t];
  __syncthreads();
  int p = blockIdx.x*256 + t;
  int b = p/NN, n = p - b*NN;
  float in[16];
  const float* fb = feature + (size_t)b*16*NN + n;
#pragma unroll
  for(int c=0;c<16;c++) in[c]=fb[(size_t)c*NN];
  float4* ft=(float4*)&g_featT[(size_t)p*16];
  ft[0]=make_float4(in[0],in[1],in[2],in[3]);
  ft[1]=make_float4(in[4],in[5],in[6],in[7]);
  ft[2]=make_float4(in[8],in[9],in[10],in[11]);
  ft[3]=make_float4(in[12],in[13],in[14],in[15]);
  float o0[16];
#pragma unroll
  for(int o=0;o<16;o++){
    float a=sb[o];
#pragma unroll
    for(int q=0;q<4;q++){
      float4 w=*(const float4*)&sW[o*16+4*q];
      a+=w.x*in[4*q]+w.y*in[4*q+1]+w.z*in[4*q+2]+w.w*in[4*q+3];
    }
    o0[o]=fmaxf(a,0.f);
  }
  float4* f0=(float4*)&g_feat0[(size_t)p*16];
  f0[0]=make_float4(o0[0],o0[1],o0[2],o0[3]);
  f0[1]=make_float4(o0[4],o0[5],o0[6],o0[7]);
  f0[2]=make_float4(o0[8],o0[9],o0[10],o0[11]);
  f0[3]=make_float4(o0[12],o0[13],o0[14],o0[15]);
}

// geometry for one point: fills fcat[16..31] (lm1 cbr), writes lrep/gdis/lg,
// returns gdis
__device__ __forceinline__ float geomB(const float* __restrict__ xb, int n, int j,
                                       int k, int p,
                                       const float* sLW, const float* sLb,
                                       float* fcat){
  float Xx=xb[3*n], Xy=xb[3*n+1], Xz=xb[3*n+2];
  float Ax=xb[3*j], Ay=xb[3*j+1], Az=xb[3*j+2];
  float rx=Xx-Ax, ry=Xy-Ay, rz=Xz-Az;
  float rxy2=rx*rx+ry*ry;
  float rdis=sqrtf(rxy2+rz*rz);
  float ralpha=atan2f(ry,rx);
  float rbeta =atan2f(rz,sqrtf(rxy2));
  float gdis=__expf(-rdis);
  g_gdis[p*KK+k]=gdis;

  float maxd=rdis, sx=Ax, sy=Ay, sz=Az;
#pragma unroll
  for(int m=1;m<16;m<<=1){
    maxd=fmaxf(maxd,__shfl_xor_sync(0xffffffffu,maxd,m));
    sx+=__shfl_xor_sync(0xffffffffu,sx,m);
    sy+=__shfl_xor_sync(0xffffffffu,sy,m);
    sz+=__shfl_xor_sync(0xffffffffu,sz,m);
  }
  float dvx=Xx-sx*0.0625f, dvy=Xy-sy*0.0625f, dvz=Xz-sz*0.0625f;
  float dalpha=atan2f(dvy,dvx);
  float dbeta =atan2f(dvz,sqrtf(dvx*dvx+dvy*dvy));
  if(k==0){
    float gn=sqrtf(Xx*Xx+Xy*Xy+Xz*Xz);
    g_lg[p]=(maxd*maxd*maxd)/(gn*gn*gn);
  }
  float lr[12]={ralpha-dalpha, rbeta-dbeta, rdis, Xx,Xy,Xz, Ax,Ay,Az, 0.f,0.f,0.f};
#pragma unroll
  for(int o=0;o<16;o++){
    float a=sLb[o];
#pragma unroll
    for(int q=0;q<3;q++){
      float4 w=*(const float4*)&sLW[o*12+4*q];
      a+=w.x*lr[4*q]+w.y*lr[4*q+1]+w.z*lr[4*q+2]+w.w*lr[4*q+3];
    }
    fcat[16+o]=fmaxf(a,0.f);
  }
  float4* lp=(float4*)&g_lrep[((size_t)p*KK+k)*16];
  lp[0]=make_float4(fcat[16],fcat[17],fcat[18],fcat[19]);
  lp[1]=make_float4(fcat[20],fcat[21],fcat[22],fcat[23]);
  lp[2]=make_float4(fcat[24],fcat[25],fcat[26],fcat[27]);
  lp[3]=make_float4(fcat[28],fcat[29],fcat[30],fcat[31]);
  return gdis;
}

// gather neighbor feature + fdis (exp of -mean|diff|)
__device__ __forceinline__ float fgather(const float* __restrict__ fjp,
                                         const float* __restrict__ fnp,
                                         float* fcat){
  const float4* fj4=(const float4*)fjp;
  const float4* fn4=(const float4*)fnp;
  float ad=0.f;
#pragma unroll
  for(int q=0;q<4;q++){
    float4 v=fj4[q], u=fn4[q];
    fcat[4*q]=v.x; fcat[4*q+1]=v.y; fcat[4*q+2]=v.z; fcat[4*q+3]=v.w;
    ad+=fabsf(u.x-v.x)+fabsf(u.y-v.y)+fabsf(u.z-v.z)+fabsf(u.w-v.w);
  }
  return __expf(-ad*0.0625f);
}

// ---------------- kernel B: 2 points per thread ---------------------------
__global__ void __launch_bounds__(256,2) kB(const float* __restrict__ xyz,
                                            const int* __restrict__ nidx,
                                            const float* __restrict__ lm1b,
                                            const float* __restrict__ p1mb){
  __shared__ __align__(16) float sLW[192];
  __shared__ __align__(16) float sFC[1152];
  __shared__ float sPT[512], sLb[16], sPb[16];
  int t=threadIdx.x;
  for(int i=t;i<192;i+=256)  sLW[i]=g_wlm1p[i];
  for(int i=t;i<1152;i+=256) sFC[i]=g_p1fc[i];
  for(int i=t;i<512;i+=256)  sPT[i]=g_wp1mt[i];
  if(t<16){ sLb[t]=lm1b[t]; sPb[t]=p1mb[t]; }
  __syncthreads();

  int pp=t>>4, k=t&15;
  int pA = blockIdx.x*32 + pp;
  int pB = pA + 16;
  int bA=pA/NN, nA=pA-bA*NN;
  int bB=pB/NN, nB=pB-bB*NN;
  int jA=nidx[pA*KK+k], jB=nidx[pB*KK+k];

  float fcatA[32], fcatB[32];
  float gdisA=geomB(xyz+(size_t)bA*NN*3,nA,jA,k,pA,sLW,sLb,fcatA);
  float gdisB=geomB(xyz+(size_t)bB*NN*3,nB,jB,k,pB,sLW,sLb,fcatB);

  float fdisA=fgather(&g_feat0[((size_t)bA*NN+jA)*16],&g_feat0[(size_t)pA*16],fcatA);
  float fdisB=fgather(&g_feat0[((size_t)bB*NN+jB)*16],&g_feat0[(size_t)pB*16],fcatB);

  float accA=0.f, accB=0.f;
#pragma unroll
  for(int o=0;o<32;o++){
    const float* w=&sFC[o*36];
    float2 wgf=*(const float2*)w;
    float s0=wgf.x*gdisA+wgf.y*fdisA;
    float s1=wgf.x*gdisB+wgf.y*fdisB;
#pragma unroll
    for(int q=0;q<8;q++){
      float4 wc=*(const float4*)(w+4+4*q);
      s0+=wc.x*fcatA[4*q]+wc.y*fcatA[4*q+1]+wc.z*fcatA[4*q+2]+wc.w*fcatA[4*q+3];
      s1+=wc.x*fcatB[4*q]+wc.y*fcatB[4*q+1]+wc.z*fcatB[4*q+2]+wc.w*fcatB[4*q+3];
    }
    float e0=__expf(s0), e1=__expf(s1);
    float t0=e0*fcatA[o], t1=e1*fcatB[o];
#pragma unroll
    for(int m=1;m<16;m<<=1){
      e0+=__shfl_xor_sync(0xffffffffu,e0,m);
      t0+=__shfl_xor_sync(0xffffffffu,t0,m);
      e1+=__shfl_xor_sync(0xffffffffu,e1,m);
      t1+=__shfl_xor_sync(0xffffffffu,t1,m);
    }
    float wp=sPT[o*16+k];
    accA+=wp*__fdividef(t0,e0);
    accB+=wp*__fdividef(t1,e1);
  }
  g_feat1[(size_t)pA*16+k]=fmaxf(accA+sPb[k],0.f);
  g_feat1[(size_t)pB*16+k]=fmaxf(accB+sPb[k],0.f);
}

// ---------------- kernel C1: 2 points per thread --------------------------
__global__ void __launch_bounds__(256,2) kC1(const float* __restrict__ xyz,
                    const int* __restrict__ nidx,
                    const float* __restrict__ lm2b, const float* __restrict__ p2mb,
                    const float* __restrict__ m2b, const float* __restrict__ scb,
                    const float* __restrict__ m3b){
  __shared__ __align__(16) float sL[256];
  __shared__ __align__(16) float sFC[1152];
  __shared__ __align__(16) float sM2[2048];
  __shared__ __align__(16) float sSC[1024];
  __shared__ __align__(16) float sM3[256];
  __shared__ float2 sPT[512];
  __shared__ float sLb[16], sPb[32], sM2b[64], sSCb[64], sM3b[64];
  int t=threadIdx.x;
  for(int i=t;i<256;i+=256)  sL[i]=g_wlm2[i];
  for(int i=t;i<1152;i+=256) sFC[i]=g_p2fc[i];
  for(int i=t;i<512;i+=256)  sPT[i]=make_float2(g_wp2mt[2*i],g_wp2mt[2*i+1]);
  for(int i=t;i<2048;i+=256) sM2[i]=g_m2t[i];
  for(int i=t;i<1024;i+=256) sSC[i]=g_sct[i];
  for(int i=t;i<256;i+=256)  sM3[i]=g_m3t[i];
  if(t<16) sLb[t]=lm2b[t];
  if(t<32) sPb[t]=p2mb[t];
  if(t<64){ sM2b[t]=m2b[t]; sSCb[t]=scb[t]; sM3b[t]=m3b[t]; }
  __syncthreads();

  int pp=t>>4, k=t&15;
  int pA=blockIdx.x*32+pp;
  int pB=pA+16;
  int bA=pA/NN, nA=pA-bA*NN;
  int bB=pB/NN, nB=pB-bB*NN;
  int jA=nidx[pA*KK+k], jB=nidx[pB*KK+k];

  // load lrep for both points
  float lrA[16], lrB[16];
  {
    const float4* lp=(const float4*)&g_lrep[((size_t)pA*KK+k)*16];
#pragma unroll
    for(int q=0;q<4;q++){ float4 v=lp[q]; lrA[4*q]=v.x; lrA[4*q+1]=v.y; lrA[4*q+2]=v.z; lrA[4*q+3]=v.w; }
  }
  {
    const float4* lp=(const float4*)&g_lrep[((size_t)pB*KK+k)*16];
#pragma unroll
    for(int q=0;q<4;q++){ float4 v=lp[q]; lrB[4*q]=v.x; lrB[4*q+1]=v.y; lrB[4*q+2]=v.z; lrB[4*q+3]=v.w; }
  }
  float fcatA[32], fcatB[32];
#pragma unroll
  for(int o=0;o<16;o++){
    float a0=sLb[o], a1=a0;
#pragma unroll
    for(int q=0;q<4;q++){
      float4 w=*(const float4*)&sL[o*16+4*q];
      a0+=w.x*lrA[4*q]+w.y*lrA[4*q+1]+w.z*lrA[4*q+2]+w.w*lrA[4*q+3];
      a1+=w.x*lrB[4*q]+w.y*lrB[4*q+1]+w.z*lrB[4*q+2]+w.w*lrB[4*q+3];
    }
    fcatA[16+o]=fmaxf(a0,0.f);
    fcatB[16+o]=fmaxf(a1,0.f);
  }
  float fdisA=fgather(&g_feat1[((size_t)bA*NN+jA)*16],&g_feat1[(size_t)pA*16],fcatA);
  float fdisB=fgather(&g_feat1[((size_t)bB*NN+jB)*16],&g_feat1[(size_t)pB*16],fcatB);
  float gdisA=g_gdis[pA*KK+k];
  float gdisB=g_gdis[pB*KK+k];

  // fused pooling2 + p2m, weights shared across the two points
  float v0A=0.f,v1A=0.f,v0B=0.f,v1B=0.f;
#pragma unroll
  for(int o=0;o<32;o++){
    const float* w=&sFC[o*36];
    float2 wgf=*(const float2*)w;
    float s0=wgf.x*gdisA+wgf.y*fdisA;
    float s1=wgf.x*gdisB+wgf.y*fdisB;
#pragma unroll
    for(int q=0;q<8;q++){
      float4 wc=*(const float4*)(w+4+4*q);
      s0+=wc.x*fcatA[4*q]+wc.y*fcatA[4*q+1]+wc.z*fcatA[4*q+2]+wc.w*fcatA[4*q+3];
      s1+=wc.x*fcatB[4*q]+wc.y*fcatB[4*q+1]+wc.z*fcatB[4*q+2]+wc.w*fcatB[4*q+3];
    }
    float e0=__expf(s0), e1=__expf(s1);
    float t0=e0*fcatA[o], t1=e1*fcatB[o];
#pragma unroll
    for(int m=1;m<16;m<<=1){
      e0+=__shfl_xor_sync(0xffffffffu,e0,m);
      t0+=__shfl_xor_sync(0xffffffffu,t0,m);
      e1+=__shfl_xor_sync(0xffffffffu,e1,m);
      t1+=__shfl_xor_sync(0xffffffffu,t1,m);
    }
    float2 wp=sPT[o*16+k];
    float f0=__fdividef(t0,e0), f1=__fdividef(t1,e1);
    v0A+=wp.x*f0; v1A+=wp.y*f0;
    v0B+=wp.x*f1; v1B+=wp.y*f1;
  }
  v0A=fmaxf(v0A+sPb[k],0.f);  v1A=fmaxf(v1A+sPb[k+16],0.f);
  v0B=fmaxf(v0B+sPb[k],0.f);  v1B=fmaxf(v1B+sPb[k+16],0.f);

  // m2 (64x32): shared weight load, both points
  float4 accA=make_float4(0.f,0.f,0.f,0.f);
  float4 accB=make_float4(0.f,0.f,0.f,0.f);
#pragma unroll
  for(int c=0;c<32;c++){
    float4 w=*(const float4*)&sM2[c*64+4*k];
    float vA=(c<16)?__shfl_sync(0xffffffffu,v0A,c,16)
                   :__shfl_sync(0xffffffffu,v1A,c-16,16);
    float vB=(c<16)?__shfl_sync(0xffffffffu,v0B,c,16)
                   :__shfl_sync(0xffffffffu,v1B,c-16,16);
    accA.x+=w.x*vA; accA.y+=w.y*vA; accA.z+=w.z*vA; accA.w+=w.w*vA;
    accB.x+=w.x*vB; accB.y+=w.y*vB; accB.z+=w.z*vB; accB.w+=w.w*vB;
  }

  int o0=4*k;
  // per-point tail (sc + m3 + h store), sequential to limit registers
#pragma unroll
  for(int pt=0;pt<2;pt++){
    int p = pt? pB:pA;
    int b = pt? bB:bA;
    int n = pt? nB:nA;
    float4 acc = pt? accB:accA;
    const float* ft=&g_featT[(size_t)p*16];
    float4 asc=make_float4(0.f,0.f,0.f,0.f);
#pragma unroll
    for(int c=0;c<16;c++){
      float fc=ft[c];
      float4 w=*(const float4*)&sSC[c*64+4*k];
      asc.x+=w.x*fc; asc.y+=w.y*fc; asc.z+=w.z*fc; asc.w+=w.w*fc;
    }
    const float* xb=xyz+(size_t)b*NN*3;
    float g3[4]={xb[3*n],xb[3*n+1],xb[3*n+2],g_lg[p]};
    float4 agc=make_float4(0.f,0.f,0.f,0.f);
#pragma unroll
    for(int c=0;c<4;c++){
      float fc=g3[c];
      float4 w=*(const float4*)&sM3[c*64+4*k];
      agc.x+=w.x*fc; agc.y+=w.y*fc; agc.z+=w.z*fc; agc.w+=w.w*fc;
    }
    float4 hl=make_float4(acc.x+sM2b[o0]+asc.x+sSCb[o0],
                          acc.y+sM2b[o0+1]+asc.y+sSCb[o0+1],
                          acc.z+sM2b[o0+2]+asc.z+sSCb[o0+2],
                          acc.w+sM2b[o0+3]+asc.w+sSCb[o0+3]);
    float4 hh=make_float4(agc.x+sM3b[o0],agc.y+sM3b[o0+1],
                          agc.z+sM3b[o0+2],agc.w+sM3b[o0+3]);
    float4* hp=(float4*)&g_h[(size_t)p*128];
    hp[k]=hl;
    hp[16+k]=hh;
  }
}

// ---------------- kernel C2: out = relu(m4 cbr(h)) ------------------------
__global__ void __launch_bounds__(256) kC2(const float* __restrict__ m4b,
                                           float* __restrict__ out){
  __shared__ __align__(16) float sW[8192];
  __shared__ __align__(16) float sh[16*132];
  __shared__ float sb[64];
  int t=threadIdx.x;
  for(int i=t;i<8192;i+=256) sW[i]=g_m4t[i];
  if(t<64) sb[t]=m4b[t];
  for(int i=t;i<512;i+=256){
    int lpt=i>>5, c4=i&31;
    float4 v=((const float4*)&g_h[((size_t)(blockIdx.x*16+lpt))*128])[c4];
    ((float4*)(sh+lpt*132))[c4]=v;
  }
  __syncthreads();

  int pp=t>>4, k=t&15;
  int p=blockIdx.x*16+pp;
  int b=p/NN, n=p-b*NN;
  const float4* hb4=(const float4*)&sh[pp*132];
  float4 acc=make_float4(0.f,0.f,0.f,0.f);
#pragma unroll
  for(int c4=0;c4<32;c4++){
    float4 h4=hb4[c4];
    float4 w0=*(const float4*)&sW[(4*c4  )*64+4*k];
    float4 w1=*(const float4*)&sW[(4*c4+1)*64+4*k];
    float4 w2=*(const float4*)&sW[(4*c4+2)*64+4*k];
    float4 w3=*(const float4*)&sW[(4*c4+3)*64+4*k];
    acc.x+=w0.x*h4.x+w1.x*h4.y+w2.x*h4.z+w3.x*h4.w;
    acc.y+=w0.y*h4.x+w1.y*h4.y+w2.y*h4.z+w3.y*h4.w;
    acc.z+=w0.z*h4.x+w1.z*h4.y+w2.z*h4.z+w3.z*h4.w;
    acc.w+=w0.w*h4.x+w1.w*h4.y+w2.w*h4.z+w3.w*h4.w;
  }
  int o0=4*k;
  size_t base=((size_t)b*64+o0)*NN+n;
  out[base]      =fmaxf(acc.x+sb[o0]  ,0.f);
  out[base+NN]   =fmaxf(acc.y+sb[o0+1],0.f);
  out[base+2*(size_t)NN]=fmaxf(acc.z+sb[o0+2],0.f);
  out[base+3*(size_t)NN]=fmaxf(acc.w+sb[o0+3],0.f);
}

// ---------------- launch ---------------------------------------------------
extern "C" void kernel_launch(void* const* d_in, const int* in_sizes, int n_in,
                              void* d_out, int out_size){
  const float* feature=(const float*)d_in[0];
  const float* xyz    =(const float*)d_in[1];
  const int*   nidx   =(const int*)  d_in[31];
  float* out=(float*)d_out;

  k_prep<<<1,256>>>((const float*)d_in[2],(const float*)d_in[3],
                    (const float*)d_in[5],(const float*)d_in[6],
                    (const float*)d_in[8],(const float*)d_in[9],
                    (const float*)d_in[11],
                    (const float*)d_in[12],(const float*)d_in[13],
                    (const float*)d_in[15],
                    (const float*)d_in[16],(const float*)d_in[17],
                    (const float*)d_in[19],(const float*)d_in[20],
                    (const float*)d_in[22],(const float*)d_in[23],
                    (const float*)d_in[25],(const float*)d_in[26],
                    (const float*)d_in[28],(const float*)d_in[29]);
  kA<<<NPTS/256,256>>>(feature,(const float*)d_in[4]);
  kB<<<NPTS/32,256>>>(xyz,nidx,(const float*)d_in[7],(const float*)d_in[14]);
  kC1<<<NPTS/32,256>>>(xyz,nidx,(const float*)d_in[10],(const float*)d_in[18],
                       (const float*)d_in[21],(const float*)d_in[24],
                       (const float*)d_in[27]);
  kC2<<<NPTS/16,256>>>((const float*)d_in[30],out);
}

// round 6
// speedup vs baseline: 1.1709x; 1.1709x over previous
#include <cuda_runtime.h>
#include <math.h>

#define BB 4
#define NN 20480
#define KK 16
#define NPTS (BB*NN)   // 81920

// ---------------- scratch (device globals, no allocation) ----------------
__device__ float g_featT[NPTS*16];
__device__ float g_feat0[NPTS*16];
__device__ float g_feat1[NPTS*16];
__device__ float g_lrep[(size_t)NPTS*KK*16];
__device__ float g_gdis[NPTS*KK];
__device__ float g_lg[NPTS];
__device__ float g_pool[(size_t)NPTS*32];   // p2m output (32 ch per point)

// preprocessed weights
__device__ float g_wm1[256];
__device__ float g_wlm1p[192];
__device__ float g_wlm2[256];
__device__ float g_p1fc[1152];
__device__ float g_wp1mt[512];
__device__ float g_p2fc[1152];
__device__ float g_wp2mt[1024];
__device__ float g_m2t[2048];   // [c][o] c<32 o<64
__device__ float g_sct[1024];   // [c][o] c<16
__device__ float g_m3t[256];    // [c][o] c<4
__device__ float g_m4t[8192];   // [c][o] c<128

// ---------------- prep ----------------------------------------------------
__global__ void k_prep(const float* m1W,const float* m1g,
                       const float* lm1W,const float* lm1g,
                       const float* lm2W,const float* lm2g,
                       const float* p1fcW,
                       const float* p1mW,const float* p1mg,
                       const float* p2fcW,
                       const float* p2mW,const float* p2mg,
                       const float* m2W,const float* m2g,
                       const float* scW,const float* scg,
                       const float* m3W,const float* m3g,
                       const float* m4W,const float* m4g)
{
  int t=threadIdx.x;
  for(int i=t;i<256;i+=256)  g_wm1[i]=m1g[i>>4]*m1W[i];
  for(int i=t;i<192;i+=256){
    int o=i/12,c=i%12;
    g_wlm1p[i]=(c<9)? lm1g[o]*lm1W[o*9+c] : 0.f;
  }
  for(int i=t;i<256;i+=256)  g_wlm2[i]=lm2g[i>>4]*lm2W[i];
  for(int i=t;i<1152;i+=256){
    int o=i/36,c=i%36; float v=0.f;
    if(c==0) v=p1fcW[o*34];
    else if(c==1) v=2.f*p1fcW[o*34+1];
    else if(c>=4) v=p1fcW[o*34+2+(c-4)];
    g_p1fc[i]=v;
  }
  for(int i=t;i<512;i+=256){ int c=i>>4,o=i&15; g_wp1mt[i]=p1mg[o]*p1mW[o*32+c]; }
  for(int i=t;i<1152;i+=256){
    int o=i/36,c=i%36; float v=0.f;
    if(c==0) v=p2fcW[o*34];
    else if(c==1) v=2.f*p2fcW[o*34+1];
    else if(c>=4) v=p2fcW[o*34+2+(c-4)];
    g_p2fc[i]=v;
  }
  for(int i=t;i<512;i+=256){
    int c=i>>4,j=i&15;
    g_wp2mt[2*i]  =p2mg[j]   *p2mW[j*32+c];
    g_wp2mt[2*i+1]=p2mg[j+16]*p2mW[(j+16)*32+c];
  }
  for(int i=t;i<2048;i+=256){int o=i>>5,c=i&31;  g_m2t[c*64+o]=m2g[o]*m2W[i];}
  for(int i=t;i<1024;i+=256){int o=i>>4,c=i&15;  g_sct[c*64+o]=scg[o]*scW[i];}
  for(int i=t;i<256;i+=256) {int o=i>>2,c=i&3;   g_m3t[c*64+o]=m3g[o]*m3W[i];}
  for(int i=t;i<8192;i+=256){int o=i>>7,c=i&127; g_m4t[c*64+o]=m4g[o]*m4W[i];}
}

// ---------------- kernel A ------------------------------------------------
__global__ void __launch_bounds__(256) kA(const float* __restrict__ feature,
                                          const float* __restrict__ m1b){
  __shared__ __align__(16) float sW[256];
  __shared__ float sb[16];
  int t=threadIdx.x;
  if(t<256) sW[t]=g_wm1[t];
  if(t<16)  sb[t]=m1b[t];
  __syncthreads();
  int p = blockIdx.x*256 + t;
  int b = p/NN, n = p - b*NN;
  float in[16];
  const float* fb = feature + (size_t)b*16*NN + n;
#pragma unroll
  for(int c=0;c<16;c++) in[c]=fb[(size_t)c*NN];
  float4* ft=(float4*)&g_featT[(size_t)p*16];
  ft[0]=make_float4(in[0],in[1],in[2],in[3]);
  ft[1]=make_float4(in[4],in[5],in[6],in[7]);
  ft[2]=make_float4(in[8],in[9],in[10],in[11]);
  ft[3]=make_float4(in[12],in[13],in[14],in[15]);
  float o0[16];
#pragma unroll
  for(int o=0;o<16;o++){
    float a=sb[o];
#pragma unroll
    for(int q=0;q<4;q++){
      float4 w=*(const float4*)&sW[o*16+4*q];
      a+=w.x*in[4*q]+w.y*in[4*q+1]+w.z*in[4*q+2]+w.w*in[4*q+3];
    }
    o0[o]=fmaxf(a,0.f);
  }
  float4* f0=(float4*)&g_feat0[(size_t)p*16];
  f0[0]=make_float4(o0[0],o0[1],o0[2],o0[3]);
  f0[1]=make_float4(o0[4],o0[5],o0[6],o0[7]);
  f0[2]=make_float4(o0[8],o0[9],o0[10],o0[11]);
  f0[3]=make_float4(o0[12],o0[13],o0[14],o0[15]);
}

// ---------------- kernel B: 1 point per thread (round-3 proven form) ------
__global__ void __launch_bounds__(256,3) kB(const float* __restrict__ xyz,
                                            const int* __restrict__ nidx,
                                            const float* __restrict__ lm1b,
                                            const float* __restrict__ p1mb){
  __shared__ __align__(16) float sLW[192];
  __shared__ __align__(16) float sFC[1152];
  __shared__ float sPT[512], sLb[16], sPb[16];
  int t=threadIdx.x;
  for(int i=t;i<192;i+=256)  sLW[i]=g_wlm1p[i];
  for(int i=t;i<1152;i+=256) sFC[i]=g_p1fc[i];
  for(int i=t;i<512;i+=256)  sPT[i]=g_wp1mt[i];
  if(t<16){ sLb[t]=lm1b[t]; sPb[t]=p1mb[t]; }
  __syncthreads();

  int pp=t>>4, k=t&15;
  int p = blockIdx.x*16 + pp;
  int b = p/NN, n = p - b*NN;
  int j = nidx[p*KK+k];
  const float* xb = xyz + (size_t)b*NN*3;
  float Xx=xb[3*n], Xy=xb[3*n+1], Xz=xb[3*n+2];
  float Ax=xb[3*j], Ay=xb[3*j+1], Az=xb[3*j+2];
  float rx=Xx-Ax, ry=Xy-Ay, rz=Xz-Az;
  float rxy2=rx*rx+ry*ry;
  float rdis=sqrtf(rxy2+rz*rz);
  float ralpha=atan2f(ry,rx);
  float rbeta =atan2f(rz,sqrtf(rxy2));
  float gdis=__expf(-rdis);
  g_gdis[p*KK+k]=gdis;

  float maxd=rdis, sx=Ax, sy=Ay, sz=Az;
#pragma unroll
  for(int m=1;m<16;m<<=1){
    maxd=fmaxf(maxd,__shfl_xor_sync(0xffffffffu,maxd,m));
    sx+=__shfl_xor_sync(0xffffffffu,sx,m);
    sy+=__shfl_xor_sync(0xffffffffu,sy,m);
    sz+=__shfl_xor_sync(0xffffffffu,sz,m);
  }
  float dvx=Xx-sx*0.0625f, dvy=Xy-sy*0.0625f, dvz=Xz-sz*0.0625f;
  float dalpha=atan2f(dvy,dvx);
  float dbeta =atan2f(dvz,sqrtf(dvx*dvx+dvy*dvy));
  if(k==0){
    float gn=sqrtf(Xx*Xx+Xy*Xy+Xz*Xz);
    g_lg[p]=(maxd*maxd*maxd)/(gn*gn*gn);
  }

  float lr[12]={ralpha-dalpha, rbeta-dbeta, rdis, Xx,Xy,Xz, Ax,Ay,Az, 0.f,0.f,0.f};
  float fcat[32];
#pragma unroll
  for(int o=0;o<16;o++){
    float a=sLb[o];
#pragma unroll
    for(int q=0;q<3;q++){
      float4 w=*(const float4*)&sLW[o*12+4*q];
      a+=w.x*lr[4*q]+w.y*lr[4*q+1]+w.z*lr[4*q+2]+w.w*lr[4*q+3];
    }
    fcat[16+o]=fmaxf(a,0.f);
  }
  float4* lp=(float4*)&g_lrep[((size_t)p*KK+k)*16];
  lp[0]=make_float4(fcat[16],fcat[17],fcat[18],fcat[19]);
  lp[1]=make_float4(fcat[20],fcat[21],fcat[22],fcat[23]);
  lp[2]=make_float4(fcat[24],fcat[25],fcat[26],fcat[27]);
  lp[3]=make_float4(fcat[28],fcat[29],fcat[30],fcat[31]);

  const float4* fj4=(const float4*)&g_feat0[((size_t)b*NN+j)*16];
  const float4* fn4=(const float4*)&g_feat0[(size_t)p*16];
  float ad=0.f;
#pragma unroll
  for(int q=0;q<4;q++){
    float4 v=fj4[q], u=fn4[q];
    fcat[4*q]=v.x; fcat[4*q+1]=v.y; fcat[4*q+2]=v.z; fcat[4*q+3]=v.w;
    ad+=fabsf(u.x-v.x)+fabsf(u.y-v.y)+fabsf(u.z-v.z)+fabsf(u.w-v.w);
  }
  float fdis=__expf(-ad*0.0625f);

  float acc=0.f;
#pragma unroll
  for(int o=0;o<32;o++){
    const float* w=&sFC[o*36];
    float2 wgf=*(const float2*)w;
    float s=wgf.x*gdis+wgf.y*fdis;
#pragma unroll
    for(int q=0;q<8;q++){
      float4 wc=*(const float4*)(w+4+4*q);
      s+=wc.x*fcat[4*q]+wc.y*fcat[4*q+1]+wc.z*fcat[4*q+2]+wc.w*fcat[4*q+3];
    }
    float e=__expf(s);
    float ts=e*fcat[o];
#pragma unroll
    for(int m=1;m<16;m<<=1){
      e +=__shfl_xor_sync(0xffffffffu,e ,m);
      ts+=__shfl_xor_sync(0xffffffffu,ts,m);
    }
    acc+=sPT[o*16+k]*__fdividef(ts,e);
  }
  g_feat1[(size_t)p*16+k]=fmaxf(acc+sPb[k],0.f);
}

// gather neighbor feature + fdis
__device__ __forceinline__ float fgather(const float* __restrict__ fjp,
                                         const float* __restrict__ fnp,
                                         float* fcat){
  const float4* fj4=(const float4*)fjp;
  const float4* fn4=(const float4*)fnp;
  float ad=0.f;
#pragma unroll
  for(int q=0;q<4;q++){
    float4 v=fj4[q], u=fn4[q];
    fcat[4*q]=v.x; fcat[4*q+1]=v.y; fcat[4*q+2]=v.z; fcat[4*q+3]=v.w;
    ad+=fabsf(u.x-v.x)+fabsf(u.y-v.y)+fabsf(u.z-v.z)+fabsf(u.w-v.w);
  }
  return __expf(-ad*0.0625f);
}

// ---------------- kernel C1: pool-only, 2 points per thread ---------------
__global__ void __launch_bounds__(256,2) kC1(const int* __restrict__ nidx,
                    const float* __restrict__ lm2b, const float* __restrict__ p2mb){
  __shared__ __align__(16) float sL[256];
  __shared__ __align__(16) float sFC[1152];
  __shared__ float2 sPT[512];
  __shared__ float sLb[16], sPb[32];
  int t=threadIdx.x;
  for(int i=t;i<256;i+=256)  sL[i]=g_wlm2[i];
  for(int i=t;i<1152;i+=256) sFC[i]=g_p2fc[i];
  for(int i=t;i<512;i+=256)  sPT[i]=make_float2(g_wp2mt[2*i],g_wp2mt[2*i+1]);
  if(t<16) sLb[t]=lm2b[t];
  if(t<32) sPb[t]=p2mb[t];
  __syncthreads();

  int pp=t>>4, k=t&15;
  int pA=blockIdx.x*32+pp;
  int pB=pA+16;
  int bA=pA/NN, bB=pB/NN;
  int jA=nidx[pA*KK+k], jB=nidx[pB*KK+k];

  float fcatA[32], fcatB[32];
  // lrep2 = relu(lm2 cbr(lrep)) for both points
  {
    float lrA[16], lrB[16];
    const float4* la=(const float4*)&g_lrep[((size_t)pA*KK+k)*16];
    const float4* lb=(const float4*)&g_lrep[((size_t)pB*KK+k)*16];
#pragma unroll
    for(int q=0;q<4;q++){
      float4 v=la[q]; lrA[4*q]=v.x; lrA[4*q+1]=v.y; lrA[4*q+2]=v.z; lrA[4*q+3]=v.w;
      float4 u=lb[q]; lrB[4*q]=u.x; lrB[4*q+1]=u.y; lrB[4*q+2]=u.z; lrB[4*q+3]=u.w;
    }
#pragma unroll
    for(int o=0;o<16;o++){
      float a0=sLb[o], a1=a0;
#pragma unroll
      for(int q=0;q<4;q++){
        float4 w=*(const float4*)&sL[o*16+4*q];
        a0+=w.x*lrA[4*q]+w.y*lrA[4*q+1]+w.z*lrA[4*q+2]+w.w*lrA[4*q+3];
        a1+=w.x*lrB[4*q]+w.y*lrB[4*q+1]+w.z*lrB[4*q+2]+w.w*lrB[4*q+3];
      }
      fcatA[16+o]=fmaxf(a0,0.f);
      fcatB[16+o]=fmaxf(a1,0.f);
    }
  }
  float fdisA=fgather(&g_feat1[((size_t)bA*NN+jA)*16],&g_feat1[(size_t)pA*16],fcatA);
  float fdisB=fgather(&g_feat1[((size_t)bB*NN+jB)*16],&g_feat1[(size_t)pB*16],fcatB);
  float gdisA=g_gdis[pA*KK+k];
  float gdisB=g_gdis[pB*KK+k];

  // fused pooling2 + p2m, weights shared across the two points
  float v0A=0.f,v1A=0.f,v0B=0.f,v1B=0.f;
#pragma unroll
  for(int o=0;o<32;o++){
    const float* w=&sFC[o*36];
    float2 wgf=*(const float2*)w;
    float s0=wgf.x*gdisA+wgf.y*fdisA;
    float s1=wgf.x*gdisB+wgf.y*fdisB;
#pragma unroll
    for(int q=0;q<8;q++){
      float4 wc=*(const float4*)(w+4+4*q);
      s0+=wc.x*fcatA[4*q]+wc.y*fcatA[4*q+1]+wc.z*fcatA[4*q+2]+wc.w*fcatA[4*q+3];
      s1+=wc.x*fcatB[4*q]+wc.y*fcatB[4*q+1]+wc.z*fcatB[4*q+2]+wc.w*fcatB[4*q+3];
    }
    float e0=__expf(s0), e1=__expf(s1);
    float t0=e0*fcatA[o], t1=e1*fcatB[o];
#pragma unroll
    for(int m=1;m<16;m<<=1){
      e0+=__shfl_xor_sync(0xffffffffu,e0,m);
      t0+=__shfl_xor_sync(0xffffffffu,t0,m);
      e1+=__shfl_xor_sync(0xffffffffu,e1,m);
      t1+=__shfl_xor_sync(0xffffffffu,t1,m);
    }
    float2 wp=sPT[o*16+k];
    float f0=__fdividef(t0,e0), f1=__fdividef(t1,e1);
    v0A+=wp.x*f0; v1A+=wp.y*f0;
    v0B+=wp.x*f1; v1B+=wp.y*f1;
  }
  g_pool[(size_t)pA*32+k]   =fmaxf(v0A+sPb[k],0.f);
  g_pool[(size_t)pA*32+16+k]=fmaxf(v1A+sPb[k+16],0.f);
  g_pool[(size_t)pB*32+k]   =fmaxf(v0B+sPb[k],0.f);
  g_pool[(size_t)pB*32+16+k]=fmaxf(v1B+sPb[k+16],0.f);
}

// ---------------- kernel C2: fused m2+sc+m3 -> h -> m4 -> out -------------
__global__ void __launch_bounds__(256) kC2(const float* __restrict__ xyz,
                                           const float* __restrict__ m2b,
                                           const float* __restrict__ scb,
                                           const float* __restrict__ m3b,
                                           const float* __restrict__ m4b,
                                           float* __restrict__ out){
  __shared__ __align__(16) float sW[8192];    // m4t
  __shared__ __align__(16) float sh[16*132];  // h staging (padded)
  __shared__ __align__(16) float sv[16*32];   // pooled vectors
  __shared__ float sb[64], sM2b[64], sSCb[64], sM3b[64];
  int t=threadIdx.x;
  for(int i=t;i<8192;i+=256) sW[i]=g_m4t[i];
  if(t<64){ sb[t]=m4b[t]; sM2b[t]=m2b[t]; sSCb[t]=scb[t]; sM3b[t]=m3b[t]; }
  if(t<128){
    float4 v=((const float4*)&g_pool[(size_t)blockIdx.x*16*32])[t];
    ((float4*)sv)[t]=v;
  }
  __syncthreads();

  int pp=t>>4, k=t&15;
  int p=blockIdx.x*16+pp;
  int b=p/NN, n=p-b*NN;
  int o0=4*k;

  // m2 (64x32): weights from global (L1/L2 resident), v broadcast from smem
  const float* vv=&sv[pp*32];
  float4 acc=make_float4(0.f,0.f,0.f,0.f);
#pragma unroll
  for(int c=0;c<32;c++){
    float vc=vv[c];
    float4 w=*(const float4*)&g_m2t[c*64+o0];
    acc.x+=w.x*vc; acc.y+=w.y*vc; acc.z+=w.z*vc; acc.w+=w.w*vc;
  }
  // sc (64x16) on raw feature
  const float* ft=&g_featT[(size_t)p*16];
  float4 asc=make_float4(0.f,0.f,0.f,0.f);
#pragma unroll
  for(int c=0;c<16;c++){
    float fc=ft[c];
    float4 w=*(const float4*)&g_sct[c*64+o0];
    asc.x+=w.x*fc; asc.y+=w.y*fc; asc.z+=w.z*fc; asc.w+=w.w*fc;
  }
  // m3 (64x4) on [xyz, lg_ratio]
  const float* xb=xyz+(size_t)b*NN*3;
  float g3[4]={xb[3*n],xb[3*n+1],xb[3*n+2],g_lg[p]};
  float4 agc=make_float4(0.f,0.f,0.f,0.f);
#pragma unroll
  for(int c=0;c<4;c++){
    float fc=g3[c];
    float4 w=*(const float4*)&g_m3t[c*64+o0];
    agc.x+=w.x*fc; agc.y+=w.y*fc; agc.z+=w.z*fc; agc.w+=w.w*fc;
  }
  float4 hl=make_float4(acc.x+sM2b[o0]+asc.x+sSCb[o0],
                        acc.y+sM2b[o0+1]+asc.y+sSCb[o0+1],
                        acc.z+sM2b[o0+2]+asc.z+sSCb[o0+2],
                        acc.w+sM2b[o0+3]+asc.w+sSCb[o0+3]);
  float4 hh=make_float4(agc.x+sM3b[o0],agc.y+sM3b[o0+1],
                        agc.z+sM3b[o0+2],agc.w+sM3b[o0+3]);
  ((float4*)(sh+pp*132))[k]=hl;
  ((float4*)(sh+pp*132))[16+k]=hh;
  __syncthreads();

  // m4 (64x128)
  const float4* hb4=(const float4*)&sh[pp*132];
  float4 a4=make_float4(0.f,0.f,0.f,0.f);
#pragma unroll
  for(int c4=0;c4<32;c4++){
    float4 h4=hb4[c4];
    float4 w0=*(const float4*)&sW[(4*c4  )*64+o0];
    float4 w1=*(const float4*)&sW[(4*c4+1)*64+o0];
    float4 w2=*(const float4*)&sW[(4*c4+2)*64+o0];
    float4 w3=*(const float4*)&sW[(4*c4+3)*64+o0];
    a4.x+=w0.x*h4.x+w1.x*h4.y+w2.x*h4.z+w3.x*h4.w;
    a4.y+=w0.y*h4.x+w1.y*h4.y+w2.y*h4.z+w3.y*h4.w;
    a4.z+=w0.z*h4.x+w1.z*h4.y+w2.z*h4.z+w3.z*h4.w;
    a4.w+=w0.w*h4.x+w1.w*h4.y+w2.w*h4.z+w3.w*h4.w;
  }
  size_t base=((size_t)b*64+o0)*NN+n;
  out[base]             =fmaxf(a4.x+sb[o0]  ,0.f);
  out[base+NN]          =fmaxf(a4.y+sb[o0+1],0.f);
  out[base+2*(size_t)NN]=fmaxf(a4.z+sb[o0+2],0.f);
  out[base+3*(size_t)NN]=fmaxf(a4.w+sb[o0+3],0.f);
}

// ---------------- launch ---------------------------------------------------
extern "C" void kernel_launch(void* const* d_in, const int* in_sizes, int n_in,
                              void* d_out, int out_size){
  const float* feature=(const float*)d_in[0];
  const float* xyz    =(const float*)d_in[1];
  const int*   nidx   =(const int*)  d_in[31];
  float* out=(float*)d_out;

  k_prep<<<1,256>>>((const float*)d_in[2],(const float*)d_in[3],
                    (const float*)d_in[5],(const float*)d_in[6],
                    (const float*)d_in[8],(const float*)d_in[9],
                    (const float*)d_in[11],
                    (const float*)d_in[12],(const float*)d_in[13],
                    (const float*)d_in[15],
                    (const float*)d_in[16],(const float*)d_in[17],
                    (const float*)d_in[19],(const float*)d_in[20],
                    (const float*)d_in[22],(const float*)d_in[23],
                    (const float*)d_in[25],(const float*)d_in[26],
                    (const float*)d_in[28],(const float*)d_in[29]);
  kA<<<NPTS/256,256>>>(feature,(const float*)d_in[4]);
  kB<<<NPTS/16,256>>>(xyz,nidx,(const float*)d_in[7],(const float*)d_in[14]);
  kC1<<<NPTS/32,256>>>(nidx,(const float*)d_in[10],(const float*)d_in[18]);
  kC2<<<NPTS/16,256>>>(xyz,(const float*)d_in[21],(const float*)d_in[24],
                       (const float*)d_in[27],(const float*)d_in[30],out);
}